// round 16
// baseline (speedup 1.0000x reference)
#include <cuda_runtime.h>
#include <math.h>
#include <stdint.h>

#define B   64
#define TE  1024
#define DE  1024
#define DD  1024
#define H   1024

__device__ float g_WaH[2][B * H];      // per-d-half Wa partials (disjoint writers)
__device__ float g_spart[16][B * TE];  // per-(h-block,wn) score partials (disjoint writers)
__device__ float g_scores[B * TE];     // softmax weights

__device__ __forceinline__ void cp16(uint32_t s, const void* g) {
    asm volatile("cp.async.cg.shared.global [%0], [%1], 16;"
                 :: "r"(s), "l"(__cvta_generic_to_global(g)) : "memory");
}
#define CP_COMMIT() asm volatile("cp.async.commit_group;" ::: "memory")
#define CP_WAIT1()  asm volatile("cp.async.wait_group 1;" ::: "memory")

__device__ __forceinline__ uint32_t smem_u32(const void* p) {
    uint32_t a;
    asm("{ .reg .u64 t; cvta.to.shared.u64 t, %1; cvt.u32.u64 %0, t; }" : "=r"(a) : "l"(p));
    return a;
}

// fast tanh: clamped exp-based; rel err ~1e-5 (invisible under tf32's 2e-4)
__device__ __forceinline__ float fast_tanh(float x) {
    x = fminf(fmaxf(x, -15.f), 15.f);
    float p = __expf(x + x);
    return __fdividef(p - 1.f, p + 1.f);
}

// ---------------------------------------------------------------------------
// K1: WaH[half][b,h] = dec[b, d-half]·Wa_w[h, d-half] (+bias on half 0)
// 128 blocks = 64 h-blocks x 2 d-halves; plain stores (unique writer/cell).
// ---------------------------------------------------------------------------
__global__ void wa_kernel(const float* __restrict__ dec,
                          const float* __restrict__ Wa_w,
                          const float* __restrict__ Wa_b) {
    const int h0 = (blockIdx.x >> 1) * 16;
    const int half = blockIdx.x & 1;
    const int dbase = half * 512;
    const int tid = threadIdx.x;
    const int hl = tid >> 4;
    const int bl = tid & 15;

    __shared__ float sW[16][65];
    __shared__ float sD[64][65];

    float acc[4] = {0.f, 0.f, 0.f, 0.f};

    for (int dc = 0; dc < 512; dc += 64) {
        const int d0 = dbase + dc;
        __syncthreads();
        #pragma unroll
        for (int i = 0; i < 4; i++) {
            int l = tid + i * 256;
            int h = l >> 6, d = l & 63;
            sW[h][d] = Wa_w[(size_t)(h0 + h) * DD + d0 + d];
        }
        #pragma unroll
        for (int i = 0; i < 16; i++) {
            int l = tid + i * 256;
            int b = l >> 6, d = l & 63;
            sD[b][d] = dec[(size_t)b * DD + d0 + d];
        }
        __syncthreads();
        #pragma unroll 8
        for (int d = 0; d < 64; d++) {
            float w = sW[hl][d];
            #pragma unroll
            for (int i = 0; i < 4; i++)
                acc[i] += w * sD[bl + 16 * i][d];
        }
    }
    const float bias = half ? 0.f : Wa_b[h0 + hl];
    #pragma unroll
    for (int i = 0; i < 4; i++)
        g_WaH[half][(size_t)(bl + 16 * i) * H + h0 + hl] = acc[i] + bias;
}

// ---------------------------------------------------------------------------
// K2: fused Ua-GEMM (mma.sync tf32) + tanh + Va reduction
//   Mainloop identical to the 700.4us build; epilogue stores disjoint
//   per-(h-block, warp-column) partials with plain STG (no atomics).
// ---------------------------------------------------------------------------
#define STG    32768
#define SB_OFF 16384
#define S_WAU  98304
#define S_VAW  98816
#define SC_SMEM 99328

__global__ __launch_bounds__(128, 2)
void score_kernel(const float* __restrict__ enc,
                  const float* __restrict__ Ua_w,
                  const float* __restrict__ Ua_b,
                  const float* __restrict__ Va_w) {
    extern __shared__ char sm[];
    const uint32_t smb = smem_u32(sm);

    const int tid  = threadIdx.x;
    const int wid  = tid >> 5;
    const int lane = tid & 31;
    const int wm = wid >> 1;
    const int wn = wid & 1;
    const int lq = lane >> 2;
    const int lr = lane & 3;

    const int b  = blockIdx.y >> 3;
    const int e0 = (blockIdx.y & 7) * 128;
    const int hb = blockIdx.x;          // 0..7
    const int h0 = hb * 128;

    const char* gA = (const char*)(enc  + ((size_t)b * TE + e0) * DE);
    const char* gB = (const char*)(Ua_w + (size_t)h0 * DE);

    const int r0   = tid >> 3;
    const int ci16 = (tid & 7) * 16;
    const uint32_t cswz = (uint32_t)ci16 ^ (uint32_t)((r0 & 7) * 16);

    uint32_t aoff[8], boff[8];
    #pragma unroll
    for (int i = 0; i < 8; i++) {
        aoff[i] = (uint32_t)(r0 + 16 * i) * 128 + cswz;
        boff[i] = SB_OFF + aoff[i];
    }

    const char* gAt = gA + (size_t)r0 * 4096 + ci16;
    const char* gBt = gB + (size_t)r0 * 4096 + ci16;

    #pragma unroll
    for (int s = 0; s < 2; s++) {
        const uint32_t base = smb + (uint32_t)s * STG;
        const size_t go = (size_t)s * 128;
        #pragma unroll
        for (int i = 0; i < 8; i++) {
            cp16(base + aoff[i], gAt + (size_t)i * 16 * 4096 + go);
            cp16(base + boff[i], gBt + (size_t)i * 16 * 4096 + go);
        }
        CP_COMMIT();
    }

    float acc[4][8][4];
    #pragma unroll
    for (int m = 0; m < 4; m++)
        #pragma unroll
        for (int n = 0; n < 8; n++)
            #pragma unroll
            for (int r = 0; r < 4; r++)
                acc[m][n][r] = 0.f;

    const uint32_t lqx = (uint32_t)(lq << 2);

    int stage = 0;
    for (int c = 0; c < 32; c++) {
        CP_WAIT1();
        __syncthreads();
        if (c + 2 < 32) {
            int ps = stage + 2; if (ps >= 3) ps -= 3;
            const uint32_t base = smb + (uint32_t)ps * STG;
            const size_t go = (size_t)(c + 2) * 128;
            #pragma unroll
            for (int i = 0; i < 8; i++) {
                cp16(base + aoff[i], gAt + (size_t)i * 16 * 4096 + go);
                cp16(base + boff[i], gBt + (size_t)i * 16 * 4096 + go);
            }
        }
        CP_COMMIT();

        const uint32_t* Aw = (const uint32_t*)(sm + (size_t)stage * STG);
        const uint32_t* Bw = (const uint32_t*)(sm + (size_t)stage * STG + SB_OFF);

        #pragma unroll
        for (int k0 = 0; k0 < 32; k0 += 8) {
            const uint32_t kx0 = ((uint32_t)(k0 + lr))     ^ lqx;
            const uint32_t kx1 = ((uint32_t)(k0 + lr + 4)) ^ lqx;
            uint32_t a[4][4], bb[8][2];
            #pragma unroll
            for (int m = 0; m < 4; m++) {
                const uint32_t r1 = (uint32_t)(wm * 64 + m * 16 + lq) * 32;
                a[m][0] = Aw[r1 + kx0];
                a[m][1] = Aw[r1 + 256 + kx0];
                a[m][2] = Aw[r1 + kx1];
                a[m][3] = Aw[r1 + 256 + kx1];
            }
            #pragma unroll
            for (int n = 0; n < 8; n++) {
                const uint32_t br = (uint32_t)(wn * 64 + n * 8 + lq) * 32;
                bb[n][0] = Bw[br + kx0];
                bb[n][1] = Bw[br + kx1];
            }
            #pragma unroll
            for (int m = 0; m < 4; m++)
                #pragma unroll
                for (int n = 0; n < 8; n++)
                    asm volatile(
                        "mma.sync.aligned.m16n8k8.row.col.f32.tf32.tf32.f32 "
                        "{%0,%1,%2,%3}, {%4,%5,%6,%7}, {%8,%9}, {%0,%1,%2,%3};\n"
                        : "+f"(acc[m][n][0]), "+f"(acc[m][n][1]),
                          "+f"(acc[m][n][2]), "+f"(acc[m][n][3])
                        : "r"(a[m][0]), "r"(a[m][1]), "r"(a[m][2]), "r"(a[m][3]),
                          "r"(bb[n][0]), "r"(bb[n][1]));
        }
        if (++stage >= 3) stage = 0;
    }

    // stage wau/vaw (sum the two Wa halves here)
    ((float*)(sm + S_WAU))[tid] = g_WaH[0][(size_t)b * H + h0 + tid]
                                + g_WaH[1][(size_t)b * H + h0 + tid]
                                + Ua_b[h0 + tid];
    ((float*)(sm + S_VAW))[tid] = Va_w[h0 + tid];
    __syncthreads();
    const float* wau = (const float*)(sm + S_WAU);
    const float* vaw = (const float*)(sm + S_VAW);

    // epilogue: fast tanh + Va reduce -> plain store to own partial slot
    float* spart = g_spart[hb * 2 + wn];
    #pragma unroll
    for (int m = 0; m < 4; m++) {
        float rs[2] = {0.f, 0.f};
        #pragma unroll
        for (int n = 0; n < 8; n++)
            #pragma unroll
            for (int r = 0; r < 4; r++) {
                int h = wn * 64 + n * 8 + 2 * lr + (r & 1);
                rs[r >> 1] += vaw[h] * fast_tanh(acc[m][n][r] + wau[h]);
            }
        #pragma unroll
        for (int rr = 0; rr < 2; rr++) {
            float s = rs[rr];
            s += __shfl_xor_sync(0xffffffffu, s, 1);
            s += __shfl_xor_sync(0xffffffffu, s, 2);
            if (lr == 0) {
                int e = e0 + wm * 64 + m * 16 + rr * 8 + lq;
                spart[(size_t)b * TE + e] = s;
            }
        }
    }
}

// ---------------------------------------------------------------------------
// K3: softmax over Te per batch (sums 16 partials while loading);
// also zeroes `out` for context's atomics.
// ---------------------------------------------------------------------------
__global__ void softmax_kernel(float* __restrict__ out) {
    const int b = blockIdx.x;
    const int tid = threadIdx.x;
    __shared__ float red[256];

    #pragma unroll
    for (int i = 0; i < 4; i++)
        out[(size_t)b * DE + tid + i * 256] = 0.f;

    float vals[4];
    float m = -1e30f;
    #pragma unroll
    for (int i = 0; i < 4; i++) {
        const size_t idx = (size_t)b * TE + tid + i * 256;
        float s = 0.f;
        #pragma unroll
        for (int p = 0; p < 16; p++)
            s += g_spart[p][idx];
        vals[i] = s;
        m = fmaxf(m, s);
    }
    red[tid] = m;
    __syncthreads();
    for (int s = 128; s > 0; s >>= 1) {
        if (tid < s) red[tid] = fmaxf(red[tid], red[tid + s]);
        __syncthreads();
    }
    float M = red[0];
    __syncthreads();

    float sum = 0.f;
    #pragma unroll
    for (int i = 0; i < 4; i++) {
        vals[i] = expf(vals[i] - M);
        sum += vals[i];
    }
    red[tid] = sum;
    __syncthreads();
    for (int s = 128; s > 0; s >>= 1) {
        if (tid < s) red[tid] += red[tid + s];
        __syncthreads();
    }
    float inv = 1.f / red[0];
    #pragma unroll
    for (int i = 0; i < 4; i++)
        g_scores[(size_t)b * TE + tid + i * 256] = vals[i] * inv;
}

// ---------------------------------------------------------------------------
// K4: context[b,d] = sum_e w[b,e] * enc[b,e,d]  [R15 version, unchanged]
// ---------------------------------------------------------------------------
__global__ void context_kernel(const float* __restrict__ enc,
                               float* __restrict__ out) {
    const int b  = blockIdx.x;
    const int ec = blockIdx.y;
    const int tid = threadIdx.x;

    __shared__ float ws[64];
    if (tid < 64) ws[tid] = g_scores[(size_t)b * TE + ec * 64 + tid];
    __syncthreads();

    const float* eb = enc + (size_t)b * TE * DE + (size_t)ec * 64 * DE + 4 * tid;
    float a0 = 0.f, a1 = 0.f, a2 = 0.f, a3 = 0.f;
    #pragma unroll 4
    for (int e = 0; e < 64; e++) {
        float we = ws[e];
        float4 v = __ldcs((const float4*)(eb + (size_t)e * DE));
        a0 += we * v.x; a1 += we * v.y; a2 += we * v.z; a3 += we * v.w;
    }
    float* dst = &out[(size_t)b * DE + 4 * tid];
    atomicAdd(dst + 0, a0);
    atomicAdd(dst + 1, a1);
    atomicAdd(dst + 2, a2);
    atomicAdd(dst + 3, a3);
}

// ---------------------------------------------------------------------------
extern "C" void kernel_launch(void* const* d_in, const int* in_sizes, int n_in,
                              void* d_out, int out_size) {
    const float* enc  = (const float*)d_in[0];
    const float* dec  = (const float*)d_in[1];
    const float* Wa_w = (const float*)d_in[2];
    const float* Wa_b = (const float*)d_in[3];
    const float* Ua_w = (const float*)d_in[4];
    const float* Ua_b = (const float*)d_in[5];
    const float* Va_w = (const float*)d_in[6];
    float* out = (float*)d_out;

    cudaFuncSetAttribute(score_kernel, cudaFuncAttributeMaxDynamicSharedMemorySize, SC_SMEM);

    wa_kernel<<<128, 256>>>(dec, Wa_w, Wa_b);
    score_kernel<<<dim3(H / 128, B * TE / 128), 128, SC_SMEM>>>(enc, Ua_w, Ua_b, Va_w);
    softmax_kernel<<<B, 256>>>(out);
    context_kernel<<<dim3(B, 16), 256>>>(enc, out);
}

// round 17
// speedup vs baseline: 1.0220x; 1.0220x over previous
#include <cuda_runtime.h>
#include <math.h>
#include <stdint.h>

#define B   64
#define TE  1024
#define DE  1024
#define DD  1024
#define H   1024

__device__ float g_WaH[4][B * H];      // per-d-quarter Wa partials (disjoint writers)
__device__ float g_spart[16][B * TE];  // per-(h-block,wn) score partials (disjoint writers)
__device__ float g_scores[B * TE];     // softmax weights

__device__ __forceinline__ void cp16(uint32_t s, const void* g) {
    asm volatile("cp.async.cg.shared.global [%0], [%1], 16;"
                 :: "r"(s), "l"(__cvta_generic_to_global(g)) : "memory");
}
#define CP_COMMIT() asm volatile("cp.async.commit_group;" ::: "memory")
#define CP_WAIT1()  asm volatile("cp.async.wait_group 1;" ::: "memory")

__device__ __forceinline__ uint32_t smem_u32(const void* p) {
    uint32_t a;
    asm("{ .reg .u64 t; cvta.to.shared.u64 t, %1; cvt.u32.u64 %0, t; }" : "=r"(a) : "l"(p));
    return a;
}

// fast tanh: clamped exp-based; rel err ~1e-5 (invisible under tf32's 2e-4)
__device__ __forceinline__ float fast_tanh(float x) {
    x = fminf(fmaxf(x, -15.f), 15.f);
    float p = __expf(x + x);
    return __fdividef(p - 1.f, p + 1.f);
}

// ---------------------------------------------------------------------------
// K1: WaH[q][b,h] = dec[b, d-quarter]·Wa_w[h, d-quarter] (+bias on q 0)
// 256 blocks = 64 h-blocks x 4 d-quarters; plain stores (unique writer/cell).
// ---------------------------------------------------------------------------
__global__ void wa_kernel(const float* __restrict__ dec,
                          const float* __restrict__ Wa_w,
                          const float* __restrict__ Wa_b) {
    const int h0 = (blockIdx.x >> 2) * 16;
    const int q  = blockIdx.x & 3;
    const int dbase = q * 256;
    const int tid = threadIdx.x;
    const int hl = tid >> 4;
    const int bl = tid & 15;

    __shared__ float sW[16][65];
    __shared__ float sD[64][65];

    float acc[4] = {0.f, 0.f, 0.f, 0.f};

    for (int dc = 0; dc < 256; dc += 64) {
        const int d0 = dbase + dc;
        __syncthreads();
        #pragma unroll
        for (int i = 0; i < 4; i++) {
            int l = tid + i * 256;
            int h = l >> 6, d = l & 63;
            sW[h][d] = Wa_w[(size_t)(h0 + h) * DD + d0 + d];
        }
        #pragma unroll
        for (int i = 0; i < 16; i++) {
            int l = tid + i * 256;
            int b = l >> 6, d = l & 63;
            sD[b][d] = dec[(size_t)b * DD + d0 + d];
        }
        __syncthreads();
        #pragma unroll 8
        for (int d = 0; d < 64; d++) {
            float w = sW[hl][d];
            #pragma unroll
            for (int i = 0; i < 4; i++)
                acc[i] += w * sD[bl + 16 * i][d];
        }
    }
    const float bias = q ? 0.f : Wa_b[h0 + hl];
    #pragma unroll
    for (int i = 0; i < 4; i++)
        g_WaH[q][(size_t)(bl + 16 * i) * H + h0 + hl] = acc[i] + bias;
}

// ---------------------------------------------------------------------------
// K2: fused Ua-GEMM (mma.sync tf32) + tanh + Va reduction
//   CTA tile 128x128, 4 warps m64n64, 3-stage cp.async, 2 CTAs/SM.
//   Mainloop byte-identical to the 700.4us build.
// ---------------------------------------------------------------------------
#define STG    32768
#define SB_OFF 16384
#define S_WAU  98304
#define S_VAW  98816
#define SC_SMEM 99328

__global__ __launch_bounds__(128, 2)
void score_kernel(const float* __restrict__ enc,
                  const float* __restrict__ Ua_w,
                  const float* __restrict__ Ua_b,
                  const float* __restrict__ Va_w) {
    extern __shared__ char sm[];
    const uint32_t smb = smem_u32(sm);

    const int tid  = threadIdx.x;
    const int wid  = tid >> 5;
    const int lane = tid & 31;
    const int wm = wid >> 1;
    const int wn = wid & 1;
    const int lq = lane >> 2;
    const int lr = lane & 3;

    const int b  = blockIdx.y >> 3;
    const int e0 = (blockIdx.y & 7) * 128;
    const int hb = blockIdx.x;          // 0..7
    const int h0 = hb * 128;

    const char* gA = (const char*)(enc  + ((size_t)b * TE + e0) * DE);
    const char* gB = (const char*)(Ua_w + (size_t)h0 * DE);

    const int r0   = tid >> 3;
    const int ci16 = (tid & 7) * 16;
    const uint32_t cswz = (uint32_t)ci16 ^ (uint32_t)((r0 & 7) * 16);

    uint32_t aoff[8], boff[8];
    #pragma unroll
    for (int i = 0; i < 8; i++) {
        aoff[i] = (uint32_t)(r0 + 16 * i) * 128 + cswz;
        boff[i] = SB_OFF + aoff[i];
    }

    const char* gAt = gA + (size_t)r0 * 4096 + ci16;
    const char* gBt = gB + (size_t)r0 * 4096 + ci16;

    #pragma unroll
    for (int s = 0; s < 2; s++) {
        const uint32_t base = smb + (uint32_t)s * STG;
        const size_t go = (size_t)s * 128;
        #pragma unroll
        for (int i = 0; i < 8; i++) {
            cp16(base + aoff[i], gAt + (size_t)i * 16 * 4096 + go);
            cp16(base + boff[i], gBt + (size_t)i * 16 * 4096 + go);
        }
        CP_COMMIT();
    }

    float acc[4][8][4];
    #pragma unroll
    for (int m = 0; m < 4; m++)
        #pragma unroll
        for (int n = 0; n < 8; n++)
            #pragma unroll
            for (int r = 0; r < 4; r++)
                acc[m][n][r] = 0.f;

    const uint32_t lqx = (uint32_t)(lq << 2);

    int stage = 0;
    for (int c = 0; c < 32; c++) {
        CP_WAIT1();
        __syncthreads();
        if (c + 2 < 32) {
            int ps = stage + 2; if (ps >= 3) ps -= 3;
            const uint32_t base = smb + (uint32_t)ps * STG;
            const size_t go = (size_t)(c + 2) * 128;
            #pragma unroll
            for (int i = 0; i < 8; i++) {
                cp16(base + aoff[i], gAt + (size_t)i * 16 * 4096 + go);
                cp16(base + boff[i], gBt + (size_t)i * 16 * 4096 + go);
            }
        }
        CP_COMMIT();

        const uint32_t* Aw = (const uint32_t*)(sm + (size_t)stage * STG);
        const uint32_t* Bw = (const uint32_t*)(sm + (size_t)stage * STG + SB_OFF);

        #pragma unroll
        for (int k0 = 0; k0 < 32; k0 += 8) {
            const uint32_t kx0 = ((uint32_t)(k0 + lr))     ^ lqx;
            const uint32_t kx1 = ((uint32_t)(k0 + lr + 4)) ^ lqx;
            uint32_t a[4][4], bb[8][2];
            #pragma unroll
            for (int m = 0; m < 4; m++) {
                const uint32_t r1 = (uint32_t)(wm * 64 + m * 16 + lq) * 32;
                a[m][0] = Aw[r1 + kx0];
                a[m][1] = Aw[r1 + 256 + kx0];
                a[m][2] = Aw[r1 + kx1];
                a[m][3] = Aw[r1 + 256 + kx1];
            }
            #pragma unroll
            for (int n = 0; n < 8; n++) {
                const uint32_t br = (uint32_t)(wn * 64 + n * 8 + lq) * 32;
                bb[n][0] = Bw[br + kx0];
                bb[n][1] = Bw[br + kx1];
            }
            #pragma unroll
            for (int m = 0; m < 4; m++)
                #pragma unroll
                for (int n = 0; n < 8; n++)
                    asm volatile(
                        "mma.sync.aligned.m16n8k8.row.col.f32.tf32.tf32.f32 "
                        "{%0,%1,%2,%3}, {%4,%5,%6,%7}, {%8,%9}, {%0,%1,%2,%3};\n"
                        : "+f"(acc[m][n][0]), "+f"(acc[m][n][1]),
                          "+f"(acc[m][n][2]), "+f"(acc[m][n][3])
                        : "r"(a[m][0]), "r"(a[m][1]), "r"(a[m][2]), "r"(a[m][3]),
                          "r"(bb[n][0]), "r"(bb[n][1]));
        }
        if (++stage >= 3) stage = 0;
    }

    // stage wau/vaw (sum the four Wa quarters here)
    ((float*)(sm + S_WAU))[tid] = g_WaH[0][(size_t)b * H + h0 + tid]
                                + g_WaH[1][(size_t)b * H + h0 + tid]
                                + g_WaH[2][(size_t)b * H + h0 + tid]
                                + g_WaH[3][(size_t)b * H + h0 + tid]
                                + Ua_b[h0 + tid];
    ((float*)(sm + S_VAW))[tid] = Va_w[h0 + tid];
    __syncthreads();
    const float* wau = (const float*)(sm + S_WAU);
    const float* vaw = (const float*)(sm + S_VAW);

    // epilogue: fast tanh + Va reduce -> plain store to own partial slot
    float* spart = g_spart[hb * 2 + wn];
    #pragma unroll
    for (int m = 0; m < 4; m++) {
        float rs[2] = {0.f, 0.f};
        #pragma unroll
        for (int n = 0; n < 8; n++)
            #pragma unroll
            for (int r = 0; r < 4; r++) {
                int h = wn * 64 + n * 8 + 2 * lr + (r & 1);
                rs[r >> 1] += vaw[h] * fast_tanh(acc[m][n][r] + wau[h]);
            }
        #pragma unroll
        for (int rr = 0; rr < 2; rr++) {
            float s = rs[rr];
            s += __shfl_xor_sync(0xffffffffu, s, 1);
            s += __shfl_xor_sync(0xffffffffu, s, 2);
            if (lr == 0) {
                int e = e0 + wm * 64 + m * 16 + rr * 8 + lq;
                spart[(size_t)b * TE + e] = s;
            }
        }
    }
}

// ---------------------------------------------------------------------------
// K3: softmax over Te per batch (sums 16 partials while loading);
// also zeroes `out` for context's atomics.
// ---------------------------------------------------------------------------
__global__ void softmax_kernel(float* __restrict__ out) {
    const int b = blockIdx.x;
    const int tid = threadIdx.x;
    __shared__ float red[256];

    #pragma unroll
    for (int i = 0; i < 4; i++)
        out[(size_t)b * DE + tid + i * 256] = 0.f;

    float vals[4];
    float m = -1e30f;
    #pragma unroll
    for (int i = 0; i < 4; i++) {
        const size_t idx = (size_t)b * TE + tid + i * 256;
        float s = 0.f;
        #pragma unroll
        for (int p = 0; p < 16; p++)
            s += g_spart[p][idx];
        vals[i] = s;
        m = fmaxf(m, s);
    }
    red[tid] = m;
    __syncthreads();
    for (int s = 128; s > 0; s >>= 1) {
        if (tid < s) red[tid] = fmaxf(red[tid], red[tid + s]);
        __syncthreads();
    }
    float M = red[0];
    __syncthreads();

    float sum = 0.f;
    #pragma unroll
    for (int i = 0; i < 4; i++) {
        vals[i] = expf(vals[i] - M);
        sum += vals[i];
    }
    red[tid] = sum;
    __syncthreads();
    for (int s = 128; s > 0; s >>= 1) {
        if (tid < s) red[tid] += red[tid + s];
        __syncthreads();
    }
    float inv = 1.f / red[0];
    #pragma unroll
    for (int i = 0; i < 4; i++)
        g_scores[(size_t)b * TE + tid + i * 256] = vals[i] * inv;
}

// ---------------------------------------------------------------------------
// K4: context[b,d] = sum_e w[b,e] * enc[b,e,d]
// 16 e-chunks of 64; unroll 8 for 8 outstanding LDG.128/thread (MLP depth).
// ---------------------------------------------------------------------------
__global__ void context_kernel(const float* __restrict__ enc,
                               float* __restrict__ out) {
    const int b  = blockIdx.x;
    const int ec = blockIdx.y;
    const int tid = threadIdx.x;

    __shared__ float ws[64];
    if (tid < 64) ws[tid] = g_scores[(size_t)b * TE + ec * 64 + tid];
    __syncthreads();

    const float* eb = enc + (size_t)b * TE * DE + (size_t)ec * 64 * DE + 4 * tid;
    float a0 = 0.f, a1 = 0.f, a2 = 0.f, a3 = 0.f;
    #pragma unroll
    for (int e0 = 0; e0 < 64; e0 += 8) {
        float4 v[8];
        #pragma unroll
        for (int j = 0; j < 8; j++)
            v[j] = __ldcs((const float4*)(eb + (size_t)(e0 + j) * DE));
        #pragma unroll
        for (int j = 0; j < 8; j++) {
            float we = ws[e0 + j];
            a0 += we * v[j].x; a1 += we * v[j].y;
            a2 += we * v[j].z; a3 += we * v[j].w;
        }
    }
    float* dst = &out[(size_t)b * DE + 4 * tid];
    atomicAdd(dst + 0, a0);
    atomicAdd(dst + 1, a1);
    atomicAdd(dst + 2, a2);
    atomicAdd(dst + 3, a3);
}

// ---------------------------------------------------------------------------
extern "C" void kernel_launch(void* const* d_in, const int* in_sizes, int n_in,
                              void* d_out, int out_size) {
    const float* enc  = (const float*)d_in[0];
    const float* dec  = (const float*)d_in[1];
    const float* Wa_w = (const float*)d_in[2];
    const float* Wa_b = (const float*)d_in[3];
    const float* Ua_w = (const float*)d_in[4];
    const float* Ua_b = (const float*)d_in[5];
    const float* Va_w = (const float*)d_in[6];
    float* out = (float*)d_out;

    cudaFuncSetAttribute(score_kernel, cudaFuncAttributeMaxDynamicSharedMemorySize, SC_SMEM);

    wa_kernel<<<256, 256>>>(dec, Wa_w, Wa_b);
    score_kernel<<<dim3(H / 128, B * TE / 128), 128, SC_SMEM>>>(enc, Ua_w, Ua_b, Va_w);
    softmax_kernel<<<B, 256>>>(out);
    context_kernel<<<dim3(B, 16), 256>>>(enc, out);
}